// round 2
// baseline (speedup 1.0000x reference)
#include <cuda_runtime.h>
#include <cuda_bf16.h>

#define N_NODES 100000
#define N_EDGES 3200000
#define IN_F    128
#define HID     3
#define OUT_F   4

// Scratch (device globals — allocation-free per harness rules)
__device__ float g_deg[N_NODES];          // degree (incl. self loop)
__device__ float g_dinv[N_NODES];         // rsqrt(deg)
__device__ float g_sxw[N_NODES * HID];    // xw * dinv[row]  (pre-scaled messages)
__device__ float g_T[N_NODES * HID];      // unnormalized aggregate (self + edge sums)

// ---------------------------------------------------------------------------
// 1) deg[i] = 1.0 (self loop counted)
__global__ void k_init_deg() {
    int i = blockIdx.x * blockDim.x + threadIdx.x;
    if (i < N_NODES) g_deg[i] = 1.0f;
}

// 2) deg[col[e]] += 1  (REDG: atomicAdd result unused)
__global__ void k_deg(const int* __restrict__ col) {
    int e = blockIdx.x * blockDim.x + threadIdx.x;
    if (e < N_EDGES) {
        unsigned c = (unsigned)col[e];
        if (c < N_NODES) atomicAdd(&g_deg[c], 1.0f);
    }
}

// 3) warp-per-node: xw = x[i] @ W (128->3), dinv = rsqrt(deg),
//    sxw = xw*dinv, T = sxw (self-loop term, non-atomic init)
__global__ void k_xw(const float* __restrict__ x, const float* __restrict__ W) {
    __shared__ float sW[IN_F * HID];
    int tid = threadIdx.x;
    for (int i = tid; i < IN_F * HID; i += blockDim.x) sW[i] = W[i];
    __syncthreads();

    int gwarp = (blockIdx.x * blockDim.x + tid) >> 5;
    int lane  = tid & 31;
    if (gwarp >= N_NODES) return;

    // lane loads x[node, 4*lane .. 4*lane+3]
    const float4 xv = *reinterpret_cast<const float4*>(
        x + (size_t)gwarp * IN_F + lane * 4);
    int k0 = lane * 4;
    const float* w0 = &sW[(k0 + 0) * HID];
    const float* w1 = &sW[(k0 + 1) * HID];
    const float* w2 = &sW[(k0 + 2) * HID];
    const float* w3 = &sW[(k0 + 3) * HID];

    float a0 = xv.x * w0[0] + xv.y * w1[0] + xv.z * w2[0] + xv.w * w3[0];
    float a1 = xv.x * w0[1] + xv.y * w1[1] + xv.z * w2[1] + xv.w * w3[1];
    float a2 = xv.x * w0[2] + xv.y * w1[2] + xv.z * w2[2] + xv.w * w3[2];

    #pragma unroll
    for (int off = 16; off > 0; off >>= 1) {
        a0 += __shfl_down_sync(0xffffffffu, a0, off);
        a1 += __shfl_down_sync(0xffffffffu, a1, off);
        a2 += __shfl_down_sync(0xffffffffu, a2, off);
    }

    if (lane == 0) {
        float dinv = rsqrtf(g_deg[gwarp]);   // deg >= 1 always (self loop)
        g_dinv[gwarp] = dinv;
        float s0 = a0 * dinv, s1 = a1 * dinv, s2 = a2 * dinv;
        int base = gwarp * HID;
        g_sxw[base + 0] = s0;  g_sxw[base + 1] = s1;  g_sxw[base + 2] = s2;
        // self-loop contribution: T starts at sxw[i]  (final agg = dinv[i]*T[i])
        g_T[base + 0] = s0;    g_T[base + 1] = s1;    g_T[base + 2] = s2;
    }
}

// 4) per edge: T[col] += sxw[row]  (3 REDG fp32 adds, L2-resident targets)
__global__ void k_edge(const int* __restrict__ ei) {
    int e = blockIdx.x * blockDim.x + threadIdx.x;
    if (e >= N_EDGES) return;
    unsigned r = (unsigned)ei[e];
    unsigned c = (unsigned)ei[N_EDGES + e];
    if (r >= N_NODES || c >= N_NODES) return;
    const float* src = &g_sxw[r * HID];
    float s0 = src[0], s1 = src[1], s2 = src[2];
    float* dst = &g_T[c * HID];
    atomicAdd(dst + 0, s0);
    atomicAdd(dst + 1, s1);
    atomicAdd(dst + 2, s2);
}

// 5) epilogue: h = relu(dinv*T + b); z = h @ Wout + bout; write (h, z)
__global__ void k_final(const float* __restrict__ b,
                        const float* __restrict__ Wout,
                        const float* __restrict__ bout,
                        float* __restrict__ out) {
    int i = blockIdx.x * blockDim.x + threadIdx.x;
    if (i >= N_NODES) return;
    float dinv = g_dinv[i];
    int base = i * HID;
    float h0 = fmaxf(g_T[base + 0] * dinv + __ldg(&b[0]), 0.0f);
    float h1 = fmaxf(g_T[base + 1] * dinv + __ldg(&b[1]), 0.0f);
    float h2 = fmaxf(g_T[base + 2] * dinv + __ldg(&b[2]), 0.0f);

    out[base + 0] = h0;
    out[base + 1] = h1;
    out[base + 2] = h2;

    float* zo = out + (size_t)N_NODES * HID + (size_t)i * OUT_F;
    #pragma unroll
    for (int j = 0; j < OUT_F; j++) {
        zo[j] = h0 * __ldg(&Wout[0 * OUT_F + j]) +
                h1 * __ldg(&Wout[1 * OUT_F + j]) +
                h2 * __ldg(&Wout[2 * OUT_F + j]) + __ldg(&bout[j]);
    }
}

extern "C" void kernel_launch(void* const* d_in, const int* in_sizes, int n_in,
                              void* d_out, int out_size) {
    // Bind inputs by element count (robust to ordering):
    // x=12,800,000  edge_index=6,400,000  W=384  b=3  Wout=12  bout=4
    const float* x    = nullptr;
    const int*   ei   = nullptr;
    const float* W    = nullptr;
    const float* b    = nullptr;
    const float* Wout = nullptr;
    const float* bout = nullptr;
    for (int i = 0; i < n_in; i++) {
        switch (in_sizes[i]) {
            case 12800000: x    = (const float*)d_in[i]; break;
            case 6400000:  ei   = (const int*)  d_in[i]; break;
            case 384:      W    = (const float*)d_in[i]; break;
            case 3:        b    = (const float*)d_in[i]; break;
            case 12:       Wout = (const float*)d_in[i]; break;
            case 4:        bout = (const float*)d_in[i]; break;
            default: break;
        }
    }

    float* out = (float*)d_out;

    const int T = 256;
    k_init_deg<<<(N_NODES + T - 1) / T, T>>>();
    k_deg<<<(N_EDGES + T - 1) / T, T>>>(ei + N_EDGES);   // col = edge_index[1]
    k_xw<<<(N_NODES * 32 + T - 1) / T, T>>>(x, W);
    k_edge<<<(N_EDGES + T - 1) / T, T>>>(ei);
    k_final<<<(N_NODES + T - 1) / T, T>>>(b, Wout, bout, out);
}

// round 3
// speedup vs baseline: 1.9925x; 1.9925x over previous
#include <cuda_runtime.h>
#include <cuda_bf16.h>

#define N_NODES 100000
#define N_EDGES 3200000
#define IN_F    128
#define HID     3
#define OUT_F   4

// Scratch (device globals — allocation-free per harness rules)
__device__ float  g_deg[N_NODES];     // degree (incl. self loop)
__device__ float  g_dinv[N_NODES];    // rsqrt(deg)
__device__ float4 g_sxw4[N_NODES];    // (xw * dinv[row], 0) — padded for 128-bit gather
__device__ float4 g_T4[N_NODES];      // unnormalized aggregate, padded for RED.128

// ---------------------------------------------------------------------------
// 1) deg[i] = 1.0 (self loop counted)
__global__ void k_init_deg() {
    int i = blockIdx.x * blockDim.x + threadIdx.x;
    if (i < N_NODES) g_deg[i] = 1.0f;
}

// 2) deg[col[e]] += 1   (4 edges per thread, int4 col load, scalar REDG)
__global__ void k_deg(const int* __restrict__ col) {
    int t = blockIdx.x * blockDim.x + threadIdx.x;
    int e = t * 4;
    if (e + 3 < N_EDGES) {
        int4 c4 = *reinterpret_cast<const int4*>(col + e);
        if ((unsigned)c4.x < N_NODES) atomicAdd(&g_deg[c4.x], 1.0f);
        if ((unsigned)c4.y < N_NODES) atomicAdd(&g_deg[c4.y], 1.0f);
        if ((unsigned)c4.z < N_NODES) atomicAdd(&g_deg[c4.z], 1.0f);
        if ((unsigned)c4.w < N_NODES) atomicAdd(&g_deg[c4.w], 1.0f);
    } else {
        for (; e < N_EDGES; e++) {
            unsigned c = (unsigned)col[e];
            if (c < N_NODES) atomicAdd(&g_deg[c], 1.0f);
        }
    }
}

// 3) warp-per-node: xw = x[i] @ W (128->3), dinv = rsqrt(deg),
//    sxw4 = (xw*dinv, 0), T4 = sxw4 (self-loop term, non-atomic init)
__global__ void k_xw(const float* __restrict__ x, const float* __restrict__ W) {
    __shared__ float sW[IN_F * HID];
    int tid = threadIdx.x;
    for (int i = tid; i < IN_F * HID; i += blockDim.x) sW[i] = W[i];
    __syncthreads();

    int gwarp = (blockIdx.x * blockDim.x + tid) >> 5;
    int lane  = tid & 31;
    if (gwarp >= N_NODES) return;

    const float4 xv = *reinterpret_cast<const float4*>(
        x + (size_t)gwarp * IN_F + lane * 4);
    int k0 = lane * 4;
    const float* w0 = &sW[(k0 + 0) * HID];
    const float* w1 = &sW[(k0 + 1) * HID];
    const float* w2 = &sW[(k0 + 2) * HID];
    const float* w3 = &sW[(k0 + 3) * HID];

    float a0 = xv.x * w0[0] + xv.y * w1[0] + xv.z * w2[0] + xv.w * w3[0];
    float a1 = xv.x * w0[1] + xv.y * w1[1] + xv.z * w2[1] + xv.w * w3[1];
    float a2 = xv.x * w0[2] + xv.y * w1[2] + xv.z * w2[2] + xv.w * w3[2];

    #pragma unroll
    for (int off = 16; off > 0; off >>= 1) {
        a0 += __shfl_down_sync(0xffffffffu, a0, off);
        a1 += __shfl_down_sync(0xffffffffu, a1, off);
        a2 += __shfl_down_sync(0xffffffffu, a2, off);
    }

    if (lane == 0) {
        float dinv = rsqrtf(g_deg[gwarp]);   // deg >= 1 always (self loop)
        g_dinv[gwarp] = dinv;
        float4 s = make_float4(a0 * dinv, a1 * dinv, a2 * dinv, 0.0f);
        g_sxw4[gwarp] = s;
        g_T4[gwarp]   = s;   // self-loop contribution
    }
}

// 4) per edge: T4[col] += sxw4[row]  (LDG.128 gather + one RED.128)
//    2 edges per thread, int2 index loads.
__global__ void k_edge(const int* __restrict__ ei) {
    int t = blockIdx.x * blockDim.x + threadIdx.x;
    int e = t * 2;
    if (e + 1 < N_EDGES) {
        int2 r2 = *reinterpret_cast<const int2*>(ei + e);
        int2 c2 = *reinterpret_cast<const int2*>(ei + N_EDGES + e);
        if ((unsigned)r2.x < N_NODES && (unsigned)c2.x < N_NODES) {
            float4 s = g_sxw4[r2.x];
            atomicAdd(&g_T4[c2.x], s);
        }
        if ((unsigned)r2.y < N_NODES && (unsigned)c2.y < N_NODES) {
            float4 s = g_sxw4[r2.y];
            atomicAdd(&g_T4[c2.y], s);
        }
    } else if (e < N_EDGES) {
        unsigned r = (unsigned)ei[e];
        unsigned c = (unsigned)ei[N_EDGES + e];
        if (r < N_NODES && c < N_NODES) {
            float4 s = g_sxw4[r];
            atomicAdd(&g_T4[c], s);
        }
    }
}

// 5) epilogue: h = relu(dinv*T + b); z = h @ Wout + bout; write (h, z)
__global__ void k_final(const float* __restrict__ b,
                        const float* __restrict__ Wout,
                        const float* __restrict__ bout,
                        float* __restrict__ out) {
    int i = blockIdx.x * blockDim.x + threadIdx.x;
    if (i >= N_NODES) return;
    float dinv = g_dinv[i];
    float4 tv = g_T4[i];
    float h0 = fmaxf(tv.x * dinv + __ldg(&b[0]), 0.0f);
    float h1 = fmaxf(tv.y * dinv + __ldg(&b[1]), 0.0f);
    float h2 = fmaxf(tv.z * dinv + __ldg(&b[2]), 0.0f);

    int base = i * HID;
    out[base + 0] = h0;
    out[base + 1] = h1;
    out[base + 2] = h2;

    float* zo = out + (size_t)N_NODES * HID + (size_t)i * OUT_F;
    #pragma unroll
    for (int j = 0; j < OUT_F; j++) {
        zo[j] = h0 * __ldg(&Wout[0 * OUT_F + j]) +
                h1 * __ldg(&Wout[1 * OUT_F + j]) +
                h2 * __ldg(&Wout[2 * OUT_F + j]) + __ldg(&bout[j]);
    }
}

extern "C" void kernel_launch(void* const* d_in, const int* in_sizes, int n_in,
                              void* d_out, int out_size) {
    // Bind inputs by element count (robust to ordering):
    // x=12,800,000  edge_index=6,400,000  W=384  b=3  Wout=12  bout=4
    const float* x    = nullptr;
    const int*   ei   = nullptr;
    const float* W    = nullptr;
    const float* b    = nullptr;
    const float* Wout = nullptr;
    const float* bout = nullptr;
    for (int i = 0; i < n_in; i++) {
        switch (in_sizes[i]) {
            case 12800000: x    = (const float*)d_in[i]; break;
            case 6400000:  ei   = (const int*)  d_in[i]; break;
            case 384:      W    = (const float*)d_in[i]; break;
            case 3:        b    = (const float*)d_in[i]; break;
            case 12:       Wout = (const float*)d_in[i]; break;
            case 4:        bout = (const float*)d_in[i]; break;
            default: break;
        }
    }

    float* out = (float*)d_out;

    const int T = 256;
    k_init_deg<<<(N_NODES + T - 1) / T, T>>>();
    k_deg<<<((N_EDGES / 4) + T - 1) / T, T>>>(ei + N_EDGES);   // col = edge_index[1]
    k_xw<<<(N_NODES * 32 + T - 1) / T, T>>>(x, W);
    k_edge<<<((N_EDGES / 2) + T - 1) / T, T>>>(ei);
    k_final<<<(N_NODES + T - 1) / T, T>>>(b, Wout, bout, out);
}

// round 4
// speedup vs baseline: 2.1263x; 1.0672x over previous
#include <cuda_runtime.h>
#include <cuda_bf16.h>

#define N_NODES 100000
#define N_EDGES 3200000
#define IN_F    128
#define HID     3
#define OUT_F   4

// Fused kernel role split
#define DEG_BLOCKS   3125    // 3125*256 threads * 4 edges = 3,200,000
#define GEMV_BLOCKS  12500   // 12500 blocks * 8 warps = 100,000 nodes

// Scratch (device globals — zero-initialized at module load; g_deg is kept
// zero at kernel_launch entry by k_scale resetting it each call)
__device__ float  g_deg[N_NODES];     // edge-degree counts (self loop added as +1 later)
__device__ float  g_dinv[N_NODES];    // rsqrt(deg+1)
__device__ float4 g_sxw4[N_NODES];    // xw (unscaled by fused kernel), then *dinv by k_scale
__device__ float4 g_T4[N_NODES];      // unnormalized aggregate (self + edge sums)

// ---------------------------------------------------------------------------
// 1) Fused: blocks [0, DEG_BLOCKS) count degrees; the rest compute xw = x@W.
//    The two roles are data-independent: atomic-bound work overlaps the
//    51 MB DRAM stream.
__global__ void k_deg_gemv(const int* __restrict__ col,
                           const float* __restrict__ x,
                           const float* __restrict__ W) {
    if (blockIdx.x < DEG_BLOCKS) {
        // ---- degree role: 4 edges per thread, int4 col load, scalar REDG
        int e = (blockIdx.x * blockDim.x + threadIdx.x) * 4;
        if (e + 3 < N_EDGES) {
            int4 c4 = *reinterpret_cast<const int4*>(col + e);
            if ((unsigned)c4.x < N_NODES) atomicAdd(&g_deg[c4.x], 1.0f);
            if ((unsigned)c4.y < N_NODES) atomicAdd(&g_deg[c4.y], 1.0f);
            if ((unsigned)c4.z < N_NODES) atomicAdd(&g_deg[c4.z], 1.0f);
            if ((unsigned)c4.w < N_NODES) atomicAdd(&g_deg[c4.w], 1.0f);
        } else {
            for (; e < N_EDGES; e++) {
                unsigned c = (unsigned)col[e];
                if (c < N_NODES) atomicAdd(&g_deg[c], 1.0f);
            }
        }
        return;
    }

    // ---- GEMV role: warp-per-node, xw = x[node] @ W (128 -> 3), unscaled
    __shared__ float sW[IN_F * HID];
    int tid = threadIdx.x;
    for (int i = tid; i < IN_F * HID; i += blockDim.x) sW[i] = W[i];
    __syncthreads();

    int node = (blockIdx.x - DEG_BLOCKS) * 8 + (tid >> 5);
    int lane = tid & 31;
    if (node >= N_NODES) return;

    const float4 xv = *reinterpret_cast<const float4*>(
        x + (size_t)node * IN_F + lane * 4);
    int k0 = lane * 4;
    const float* w0 = &sW[(k0 + 0) * HID];
    const float* w1 = &sW[(k0 + 1) * HID];
    const float* w2 = &sW[(k0 + 2) * HID];
    const float* w3 = &sW[(k0 + 3) * HID];

    float a0 = xv.x * w0[0] + xv.y * w1[0] + xv.z * w2[0] + xv.w * w3[0];
    float a1 = xv.x * w0[1] + xv.y * w1[1] + xv.z * w2[1] + xv.w * w3[1];
    float a2 = xv.x * w0[2] + xv.y * w1[2] + xv.z * w2[2] + xv.w * w3[2];

    #pragma unroll
    for (int off = 16; off > 0; off >>= 1) {
        a0 += __shfl_down_sync(0xffffffffu, a0, off);
        a1 += __shfl_down_sync(0xffffffffu, a1, off);
        a2 += __shfl_down_sync(0xffffffffu, a2, off);
    }

    if (lane == 0) {
        g_sxw4[node] = make_float4(a0, a1, a2, 0.0f);
    }
}

// ---------------------------------------------------------------------------
// 2) Per node: dinv = rsqrt(deg+1); scale sxw4 in place; seed T4 with the
//    self-loop term; reset g_deg for the next replay (zero-at-entry invariant).
__global__ void k_scale() {
    int i = blockIdx.x * blockDim.x + threadIdx.x;
    if (i >= N_NODES) return;
    float dinv = rsqrtf(g_deg[i] + 1.0f);   // +1 = self loop
    g_deg[i] = 0.0f;                        // reset for next graph replay
    g_dinv[i] = dinv;
    float4 s = g_sxw4[i];
    s.x *= dinv; s.y *= dinv; s.z *= dinv;
    g_sxw4[i] = s;
    g_T4[i]   = s;                          // self-loop contribution
}

// ---------------------------------------------------------------------------
// 3) Per edge: T4[col] += sxw4[row].  4 edges/thread, int4 index loads,
//    LDG.128 gather + RED.128 per edge.
__global__ void k_edge(const int* __restrict__ ei) {
    int e = (blockIdx.x * blockDim.x + threadIdx.x) * 4;
    if (e + 3 < N_EDGES) {
        int4 r4 = *reinterpret_cast<const int4*>(ei + e);
        int4 c4 = *reinterpret_cast<const int4*>(ei + N_EDGES + e);
        if ((unsigned)r4.x < N_NODES && (unsigned)c4.x < N_NODES)
            atomicAdd(&g_T4[c4.x], g_sxw4[r4.x]);
        if ((unsigned)r4.y < N_NODES && (unsigned)c4.y < N_NODES)
            atomicAdd(&g_T4[c4.y], g_sxw4[r4.y]);
        if ((unsigned)r4.z < N_NODES && (unsigned)c4.z < N_NODES)
            atomicAdd(&g_T4[c4.z], g_sxw4[r4.z]);
        if ((unsigned)r4.w < N_NODES && (unsigned)c4.w < N_NODES)
            atomicAdd(&g_T4[c4.w], g_sxw4[r4.w]);
    } else {
        for (; e < N_EDGES; e++) {
            unsigned r = (unsigned)ei[e];
            unsigned c = (unsigned)ei[N_EDGES + e];
            if (r < N_NODES && c < N_NODES)
                atomicAdd(&g_T4[c], g_sxw4[r]);
        }
    }
}

// ---------------------------------------------------------------------------
// 4) Epilogue: h = relu(dinv*T + b); z = h @ Wout + bout; write (h, z)
__global__ void k_final(const float* __restrict__ b,
                        const float* __restrict__ Wout,
                        const float* __restrict__ bout,
                        float* __restrict__ out) {
    int i = blockIdx.x * blockDim.x + threadIdx.x;
    if (i >= N_NODES) return;
    float dinv = g_dinv[i];
    float4 tv = g_T4[i];
    float h0 = fmaxf(tv.x * dinv + __ldg(&b[0]), 0.0f);
    float h1 = fmaxf(tv.y * dinv + __ldg(&b[1]), 0.0f);
    float h2 = fmaxf(tv.z * dinv + __ldg(&b[2]), 0.0f);

    int base = i * HID;
    out[base + 0] = h0;
    out[base + 1] = h1;
    out[base + 2] = h2;

    float4 z;
    z.x = h0 * __ldg(&Wout[0])  + h1 * __ldg(&Wout[4])  + h2 * __ldg(&Wout[8])  + __ldg(&bout[0]);
    z.y = h0 * __ldg(&Wout[1])  + h1 * __ldg(&Wout[5])  + h2 * __ldg(&Wout[9])  + __ldg(&bout[1]);
    z.z = h0 * __ldg(&Wout[2])  + h1 * __ldg(&Wout[6])  + h2 * __ldg(&Wout[10]) + __ldg(&bout[2]);
    z.w = h0 * __ldg(&Wout[3])  + h1 * __ldg(&Wout[7])  + h2 * __ldg(&Wout[11]) + __ldg(&bout[3]);
    // z region starts at 300000 floats = 1.2MB offset -> 16B aligned
    *reinterpret_cast<float4*>(out + (size_t)N_NODES * HID + (size_t)i * OUT_F) = z;
}

extern "C" void kernel_launch(void* const* d_in, const int* in_sizes, int n_in,
                              void* d_out, int out_size) {
    // Bind inputs by element count (robust to ordering):
    // x=12,800,000  edge_index=6,400,000  W=384  b=3  Wout=12  bout=4
    const float* x    = nullptr;
    const int*   ei   = nullptr;
    const float* W    = nullptr;
    const float* b    = nullptr;
    const float* Wout = nullptr;
    const float* bout = nullptr;
    for (int i = 0; i < n_in; i++) {
        switch (in_sizes[i]) {
            case 12800000: x    = (const float*)d_in[i]; break;
            case 6400000:  ei   = (const int*)  d_in[i]; break;
            case 384:      W    = (const float*)d_in[i]; break;
            case 3:        b    = (const float*)d_in[i]; break;
            case 12:       Wout = (const float*)d_in[i]; break;
            case 4:        bout = (const float*)d_in[i]; break;
            default: break;
        }
    }

    float* out = (float*)d_out;

    const int T = 256;
    k_deg_gemv<<<DEG_BLOCKS + GEMV_BLOCKS, T>>>(ei + N_EDGES, x, W);
    k_scale<<<(N_NODES + T - 1) / T, T>>>();
    k_edge<<<((N_EDGES / 4) + T - 1) / T, T>>>(ei);
    k_final<<<(N_NODES + T - 1) / T, T>>>(b, Wout, bout, out);
}

// round 5
// speedup vs baseline: 2.3546x; 1.1074x over previous
#include <cuda_runtime.h>
#include <cuda_bf16.h>

#define N_NODES 100000
#define N_EDGES 3200000
#define IN_F    128
#define HID     3
#define OUT_F   4

// Fused kernel: every 5th block does degree atomics, the rest do the GEMV.
// 15625 blocks total = 3125 deg + 12500 gemv, interleaved so both roles are
// present in every scheduling wave (deg = atomic/LTS-bound, gemv = DRAM-bound).
#define FUSED_BLOCKS 15625

// Scratch (device globals — zero-initialized at module load; g_deg is kept
// zero at kernel_launch entry by k_scale resetting it each call)
__device__ float  g_deg[N_NODES];     // edge-degree counts (self loop added as +1 later)
__device__ float  g_dinv[N_NODES];    // rsqrt(deg+1)
__device__ float4 g_sxw4[N_NODES];    // xw (unscaled by fused kernel), then *dinv by k_scale
__device__ float4 g_T4[N_NODES];      // unnormalized aggregate (self + edge sums)

// ---------------------------------------------------------------------------
// 1) Fused: role interleaved by blockIdx % 5.
__global__ void k_deg_gemv(const int* __restrict__ col,
                           const float* __restrict__ x,
                           const float* __restrict__ W) {
    int q = blockIdx.x / 5;
    int r = blockIdx.x % 5;

    if (r == 0) {
        // ---- degree role (block q of 3125): 4 edges/thread, int4 col load
        int e = (q * blockDim.x + threadIdx.x) * 4;
        if (e + 3 < N_EDGES) {
            int4 c4 = *reinterpret_cast<const int4*>(col + e);
            if ((unsigned)c4.x < N_NODES) atomicAdd(&g_deg[c4.x], 1.0f);
            if ((unsigned)c4.y < N_NODES) atomicAdd(&g_deg[c4.y], 1.0f);
            if ((unsigned)c4.z < N_NODES) atomicAdd(&g_deg[c4.z], 1.0f);
            if ((unsigned)c4.w < N_NODES) atomicAdd(&g_deg[c4.w], 1.0f);
        } else {
            for (; e < N_EDGES; e++) {
                unsigned c = (unsigned)col[e];
                if (c < N_NODES) atomicAdd(&g_deg[c], 1.0f);
            }
        }
        return;
    }

    // ---- GEMV role (block g of 12500): warp-per-node, xw = x[node] @ W
    __shared__ float sW[IN_F * HID];
    int tid = threadIdx.x;
    for (int i = tid; i < IN_F * HID; i += blockDim.x) sW[i] = W[i];
    __syncthreads();

    int g = q * 4 + (r - 1);
    int node = g * 8 + (tid >> 5);
    int lane = tid & 31;
    if (node >= N_NODES) return;

    const float4 xv = *reinterpret_cast<const float4*>(
        x + (size_t)node * IN_F + lane * 4);
    int k0 = lane * 4;
    const float* w0 = &sW[(k0 + 0) * HID];
    const float* w1 = &sW[(k0 + 1) * HID];
    const float* w2 = &sW[(k0 + 2) * HID];
    const float* w3 = &sW[(k0 + 3) * HID];

    float a0 = xv.x * w0[0] + xv.y * w1[0] + xv.z * w2[0] + xv.w * w3[0];
    float a1 = xv.x * w0[1] + xv.y * w1[1] + xv.z * w2[1] + xv.w * w3[1];
    float a2 = xv.x * w0[2] + xv.y * w1[2] + xv.z * w2[2] + xv.w * w3[2];

    #pragma unroll
    for (int off = 16; off > 0; off >>= 1) {
        a0 += __shfl_down_sync(0xffffffffu, a0, off);
        a1 += __shfl_down_sync(0xffffffffu, a1, off);
        a2 += __shfl_down_sync(0xffffffffu, a2, off);
    }

    if (lane == 0) {
        g_sxw4[node] = make_float4(a0, a1, a2, 0.0f);
    }
}

// ---------------------------------------------------------------------------
// 2) Per node (4 nodes/thread, vectorized): dinv = rsqrt(deg+1); scale sxw4;
//    seed T4 with self-loop term; reset g_deg for next replay.
__global__ void k_scale() {
    int t = blockIdx.x * blockDim.x + threadIdx.x;
    int i = t * 4;
    if (i + 3 >= N_NODES) {
        for (; i < N_NODES; i++) {
            float dinv = rsqrtf(g_deg[i] + 1.0f);
            g_deg[i] = 0.0f;
            g_dinv[i] = dinv;
            float4 s = g_sxw4[i];
            s.x *= dinv; s.y *= dinv; s.z *= dinv;
            g_sxw4[i] = s;
            g_T4[i]   = s;
        }
        return;
    }
    float4 d4 = *reinterpret_cast<float4*>(&g_deg[i]);
    float4 dv;
    dv.x = rsqrtf(d4.x + 1.0f);
    dv.y = rsqrtf(d4.y + 1.0f);
    dv.z = rsqrtf(d4.z + 1.0f);
    dv.w = rsqrtf(d4.w + 1.0f);
    *reinterpret_cast<float4*>(&g_deg[i])  = make_float4(0.f, 0.f, 0.f, 0.f);
    *reinterpret_cast<float4*>(&g_dinv[i]) = dv;

    float4 s0 = g_sxw4[i + 0];
    float4 s1 = g_sxw4[i + 1];
    float4 s2 = g_sxw4[i + 2];
    float4 s3 = g_sxw4[i + 3];
    s0.x *= dv.x; s0.y *= dv.x; s0.z *= dv.x;
    s1.x *= dv.y; s1.y *= dv.y; s1.z *= dv.y;
    s2.x *= dv.z; s2.y *= dv.z; s2.z *= dv.z;
    s3.x *= dv.w; s3.y *= dv.w; s3.z *= dv.w;
    g_sxw4[i + 0] = s0;  g_T4[i + 0] = s0;
    g_sxw4[i + 1] = s1;  g_T4[i + 1] = s1;
    g_sxw4[i + 2] = s2;  g_T4[i + 2] = s2;
    g_sxw4[i + 3] = s3;  g_T4[i + 3] = s3;
}

// ---------------------------------------------------------------------------
// 3) Per edge: T4[col] += sxw4[row].  4 edges/thread, int4 index loads,
//    LDG.128 gather + RED.128 per edge.
__global__ void k_edge(const int* __restrict__ ei) {
    int e = (blockIdx.x * blockDim.x + threadIdx.x) * 4;
    if (e + 3 < N_EDGES) {
        int4 r4 = *reinterpret_cast<const int4*>(ei + e);
        int4 c4 = *reinterpret_cast<const int4*>(ei + N_EDGES + e);
        if ((unsigned)r4.x < N_NODES && (unsigned)c4.x < N_NODES)
            atomicAdd(&g_T4[c4.x], g_sxw4[r4.x]);
        if ((unsigned)r4.y < N_NODES && (unsigned)c4.y < N_NODES)
            atomicAdd(&g_T4[c4.y], g_sxw4[r4.y]);
        if ((unsigned)r4.z < N_NODES && (unsigned)c4.z < N_NODES)
            atomicAdd(&g_T4[c4.z], g_sxw4[r4.z]);
        if ((unsigned)r4.w < N_NODES && (unsigned)c4.w < N_NODES)
            atomicAdd(&g_T4[c4.w], g_sxw4[r4.w]);
    } else {
        for (; e < N_EDGES; e++) {
            unsigned r = (unsigned)ei[e];
            unsigned c = (unsigned)ei[N_EDGES + e];
            if (r < N_NODES && c < N_NODES)
                atomicAdd(&g_T4[c], g_sxw4[r]);
        }
    }
}

// ---------------------------------------------------------------------------
// 4) Epilogue (4 nodes/thread, fully vectorized):
//    h = relu(dinv*T + b); z = h @ Wout + bout; write (h, z)
__global__ void k_final(const float* __restrict__ b,
                        const float* __restrict__ Wout,
                        const float* __restrict__ bout,
                        float* __restrict__ out) {
    int t = blockIdx.x * blockDim.x + threadIdx.x;
    int i = t * 4;
    if (i >= N_NODES) return;

    float b0 = __ldg(&b[0]), b1 = __ldg(&b[1]), b2 = __ldg(&b[2]);
    float w00 = __ldg(&Wout[0]),  w01 = __ldg(&Wout[1]),  w02 = __ldg(&Wout[2]),  w03 = __ldg(&Wout[3]);
    float w10 = __ldg(&Wout[4]),  w11 = __ldg(&Wout[5]),  w12 = __ldg(&Wout[6]),  w13 = __ldg(&Wout[7]);
    float w20 = __ldg(&Wout[8]),  w21 = __ldg(&Wout[9]),  w22 = __ldg(&Wout[10]), w23 = __ldg(&Wout[11]);
    float z0 = __ldg(&bout[0]), z1 = __ldg(&bout[1]), z2 = __ldg(&bout[2]), z3 = __ldg(&bout[3]);

    float4 dv = *reinterpret_cast<const float4*>(&g_dinv[i]);
    float4 t0 = g_T4[i + 0];
    float4 t1 = g_T4[i + 1];
    float4 t2 = g_T4[i + 2];
    float4 t3 = g_T4[i + 3];

    float h[4][3];
    h[0][0] = fmaxf(t0.x * dv.x + b0, 0.f); h[0][1] = fmaxf(t0.y * dv.x + b1, 0.f); h[0][2] = fmaxf(t0.z * dv.x + b2, 0.f);
    h[1][0] = fmaxf(t1.x * dv.y + b0, 0.f); h[1][1] = fmaxf(t1.y * dv.y + b1, 0.f); h[1][2] = fmaxf(t1.z * dv.y + b2, 0.f);
    h[2][0] = fmaxf(t2.x * dv.z + b0, 0.f); h[2][1] = fmaxf(t2.y * dv.z + b1, 0.f); h[2][2] = fmaxf(t2.z * dv.z + b2, 0.f);
    h[3][0] = fmaxf(t3.x * dv.w + b0, 0.f); h[3][1] = fmaxf(t3.y * dv.w + b1, 0.f); h[3][2] = fmaxf(t3.z * dv.w + b2, 0.f);

    // h: 12 contiguous floats at out + i*3 (i%4==0 -> 48B aligned -> 16B ok)
    float* ho = out + (size_t)i * HID;
    *reinterpret_cast<float4*>(ho + 0) = make_float4(h[0][0], h[0][1], h[0][2], h[1][0]);
    *reinterpret_cast<float4*>(ho + 4) = make_float4(h[1][1], h[1][2], h[2][0], h[2][1]);
    *reinterpret_cast<float4*>(ho + 8) = make_float4(h[2][2], h[3][0], h[3][1], h[3][2]);

    // z: 16 contiguous floats at out + 300000 + i*4
    float* zo = out + (size_t)N_NODES * HID + (size_t)i * OUT_F;
    #pragma unroll
    for (int n = 0; n < 4; n++) {
        float4 z;
        z.x = h[n][0] * w00 + h[n][1] * w10 + h[n][2] * w20 + z0;
        z.y = h[n][0] * w01 + h[n][1] * w11 + h[n][2] * w21 + z1;
        z.z = h[n][0] * w02 + h[n][1] * w12 + h[n][2] * w22 + z2;
        z.w = h[n][0] * w03 + h[n][1] * w13 + h[n][2] * w23 + z3;
        *reinterpret_cast<float4*>(zo + n * 4) = z;
    }
}

extern "C" void kernel_launch(void* const* d_in, const int* in_sizes, int n_in,
                              void* d_out, int out_size) {
    // Bind inputs by element count (robust to ordering):
    // x=12,800,000  edge_index=6,400,000  W=384  b=3  Wout=12  bout=4
    const float* x    = nullptr;
    const int*   ei   = nullptr;
    const float* W    = nullptr;
    const float* b    = nullptr;
    const float* Wout = nullptr;
    const float* bout = nullptr;
    for (int i = 0; i < n_in; i++) {
        switch (in_sizes[i]) {
            case 12800000: x    = (const float*)d_in[i]; break;
            case 6400000:  ei   = (const int*)  d_in[i]; break;
            case 384:      W    = (const float*)d_in[i]; break;
            case 3:        b    = (const float*)d_in[i]; break;
            case 12:       Wout = (const float*)d_in[i]; break;
            case 4:        bout = (const float*)d_in[i]; break;
            default: break;
        }
    }

    float* out = (float*)d_out;

    const int T = 256;
    k_deg_gemv<<<FUSED_BLOCKS, T>>>(ei + N_EDGES, x, W);
    k_scale<<<((N_NODES / 4) + T - 1) / T, T>>>();
    k_edge<<<((N_EDGES / 4) + T - 1) / T, T>>>(ei);
    k_final<<<((N_NODES / 4) + T - 1) / T, T>>>(b, Wout, bout, out);
}